// round 7
// baseline (speedup 1.0000x reference)
#include <cuda_runtime.h>

// x1:   (16, 1, 224, 224) fp32
// W:    (288, 1, 3, 3)    fp32
// bias: (1, 288, 222, 222) fp32
// out:  (16, 288, 222, 222) fp32 = relu(conv_valid(x1, W) + bias)

#define B_      16
#define COUT_   288
#define HIN_    224
#define WIN_    224
#define HOUT_   222
#define WOUT_   222
#define PLANE_  (HOUT_ * WOUT_)   // 49284
#define RPB     6                 // output rows per CTA (222 = 37*6)
#define IROWS   (RPB + 2)         // 8 input rows

__global__ __launch_bounds__(224, 5) void conv_bias_relu_kernel(
    const float* __restrict__ x,
    const float* __restrict__ Wt,
    const float* __restrict__ bias,
    float* __restrict__ out)
{
    // Weights padded to 12 floats/channel: 2x LDS.128 + 1x LDS.32 per channel.
    __shared__ __align__(16) float sW[COUT_ * 12];   // 13824 B
    __shared__ float sIn[IROWS][WIN_];               //  7168 B

    const int hg = blockIdx.x;           // 0..36  (row group)
    const int b  = blockIdx.y;           // 0..15
    const int t  = threadIdx.x;          // 0..223
    const int h0 = hg * RPB;

    // Cooperative weight load with 9->12 padding.
    for (int i = t; i < COUT_ * 9; i += 224) {
        int c = i / 9, j = i - c * 9;
        sW[c * 12 + j] = Wt[i];
    }

    // Cooperative load of the 8 input rows this CTA needs (each thread = 1 col).
    const float* xb = x + b * (HIN_ * WIN_);         // < 2^31, 32-bit math
    #pragma unroll
    for (int r = 0; r < IROWS; r++) sIn[r][t] = xb[(h0 + r) * WIN_ + t];

    __syncthreads();

    if (t >= WOUT_) return;

    // 24 taps in registers: rows h0..h0+7, cols t..t+2. Invariant over channels.
    float tap[IROWS][3];
    #pragma unroll
    for (int r = 0; r < IROWS; r++) {
        tap[r][0] = sIn[r][t];
        tap[r][1] = sIn[r][t + 1];
        tap[r][2] = sIn[r][t + 2];
    }

    // All offsets fit in 32 bits: out total = 227M elems, bias = 14.2M elems.
    const int ofs = h0 * WOUT_ + t;
    const float* bp = bias + ofs;                    // += PLANE_ per channel
    float*       op = out + b * (COUT_ * PLANE_) + ofs;

    #pragma unroll 2
    for (int c = 0; c < COUT_; c++) {
        const float4 wA = *reinterpret_cast<const float4*>(&sW[c * 12]);     // w0..w3
        const float4 wB = *reinterpret_cast<const float4*>(&sW[c * 12 + 4]); // w4..w7
        const float  w8 = sW[c * 12 + 8];

        #pragma unroll
        for (int r = 0; r < RPB; r++) {
            float y = tap[r][0] * wA.x;
            y = fmaf(tap[r    ][1], wA.y, y);
            y = fmaf(tap[r    ][2], wA.z, y);
            y = fmaf(tap[r + 1][0], wA.w, y);
            y = fmaf(tap[r + 1][1], wB.x, y);
            y = fmaf(tap[r + 1][2], wB.y, y);
            y = fmaf(tap[r + 2][0], wB.z, y);
            y = fmaf(tap[r + 2][1], wB.w, y);
            y = fmaf(tap[r + 2][2], w8,  y);
            y += __ldg(bp + r * WOUT_);
            op[r * WOUT_] = fmaxf(y, 0.0f);
        }
        bp += PLANE_;
        op += PLANE_;
    }
}

extern "C" void kernel_launch(void* const* d_in, const int* in_sizes, int n_in,
                              void* d_out, int out_size)
{
    const float* x    = (const float*)d_in[0];
    const float* Wt   = (const float*)d_in[1];
    const float* bias = (const float*)d_in[2];
    float*       out  = (float*)d_out;

    dim3 grid(HOUT_ / RPB, B_);   // 37 x 16 = 592 CTAs
    dim3 block(224);              // 7 warps
    conv_bias_relu_kernel<<<grid, block>>>(x, Wt, bias, out);
}

// round 8
// speedup vs baseline: 1.0369x; 1.0369x over previous
#include <cuda_runtime.h>

// x1:   (16, 1, 224, 224) fp32
// W:    (288, 1, 3, 3)    fp32
// bias: (1, 288, 222, 222) fp32
// out:  (16, 288, 222, 222) fp32 = relu(conv_valid(x1, W) + bias)

#define B_      16
#define COUT_   288
#define HIN_    224
#define WIN_    224
#define HOUT_   222
#define WOUT_   222
#define PLANE_  (HOUT_ * WOUT_)   // 49284
#define ROWS_CTA 6                // 6 output rows per CTA (222 = 37*6)
#define IROWS   (ROWS_CTA + 2)    // 8 input rows
#define NPAIR   111               // float2 pixel pairs per row (222/2)

__global__ __launch_bounds__(256, 4) void conv_bias_relu_kernel(
    const float* __restrict__ x,
    const float* __restrict__ Wt,
    const float* __restrict__ bias,
    float* __restrict__ out)
{
    // Weights padded to 12 floats/channel: 2x LDS.128 + 1x LDS.32 per channel.
    __shared__ __align__(16) float sW[COUT_ * 12];    // 13824 B
    __shared__ __align__(8)  float sIn[IROWS][WIN_];  //  7168 B

    const int hg = blockIdx.x;           // 0..36
    const int b  = blockIdx.y;           // 0..15
    const int t  = threadIdx.x;          // 0..255
    const int h0 = hg * ROWS_CTA;

    // Cooperative weight load with 9->12 padding.
    for (int i = t; i < COUT_ * 9; i += 256) {
        int c = i / 9, j = i - c * 9;
        sW[c * 12 + j] = Wt[i];
    }

    // Cooperative load of the 8 input rows (threads 0..223 each take one column).
    const float* xb = x + b * (HIN_ * WIN_);
    if (t < WIN_) {
        #pragma unroll
        for (int r = 0; r < IROWS; r++) sIn[r][t] = xb[(h0 + r) * WIN_ + t];
    }

    __syncthreads();

    // Warp-aligned split: warps 0-3 -> rows h0..h0+2, warps 4-7 -> rows h0+3..h0+5.
    const int half = t >> 7;             // 0 or 1
    const int u    = t & 127;            // pair index; active if < 111
    if (u >= NPAIR) return;

    // Taps: 5 input rows x 4 consecutive cols (2u..2u+3), invariant over channels.
    float tap[5][4];
    #pragma unroll
    for (int r = 0; r < 5; r++) {
        float2 a = *reinterpret_cast<const float2*>(&sIn[half * 3 + r][2 * u]);
        float2 c = *reinterpret_cast<const float2*>(&sIn[half * 3 + r][2 * u + 2]);
        tap[r][0] = a.x; tap[r][1] = a.y; tap[r][2] = c.x; tap[r][3] = c.y;
    }

    // 32-bit offsets (max tensor 227M elems < 2^31).
    const int ofs = (h0 + half * 3) * WOUT_ + 2 * u;          // 8B aligned
    const float* bp = bias + ofs;
    float*       op = out + b * (COUT_ * PLANE_) + ofs;

    #pragma unroll 2
    for (int c = 0; c < COUT_; c++) {
        const float4 wA = *reinterpret_cast<const float4*>(&sW[c * 12]);     // w0..w3
        const float4 wB = *reinterpret_cast<const float4*>(&sW[c * 12 + 4]); // w4..w7
        const float  w8 = sW[c * 12 + 8];

        #pragma unroll
        for (int r = 0; r < 3; r++) {
            float y0, y1;
            y0 = tap[r][0] * wA.x;               y1 = tap[r][1] * wA.x;
            y0 = fmaf(tap[r][1], wA.y, y0);      y1 = fmaf(tap[r][2], wA.y, y1);
            y0 = fmaf(tap[r][2], wA.z, y0);      y1 = fmaf(tap[r][3], wA.z, y1);
            y0 = fmaf(tap[r+1][0], wA.w, y0);    y1 = fmaf(tap[r+1][1], wA.w, y1);
            y0 = fmaf(tap[r+1][1], wB.x, y0);    y1 = fmaf(tap[r+1][2], wB.x, y1);
            y0 = fmaf(tap[r+1][2], wB.y, y0);    y1 = fmaf(tap[r+1][3], wB.y, y1);
            y0 = fmaf(tap[r+2][0], wB.z, y0);    y1 = fmaf(tap[r+2][1], wB.z, y1);
            y0 = fmaf(tap[r+2][1], wB.w, y0);    y1 = fmaf(tap[r+2][2], wB.w, y1);
            y0 = fmaf(tap[r+2][2], w8,  y0);     y1 = fmaf(tap[r+2][3], w8,  y1);

            const float2 bv = __ldg(reinterpret_cast<const float2*>(bp + r * WOUT_));
            float2 o;
            o.x = fmaxf(y0 + bv.x, 0.0f);
            o.y = fmaxf(y1 + bv.y, 0.0f);
            *reinterpret_cast<float2*>(op + r * WOUT_) = o;
        }
        bp += PLANE_;
        op += PLANE_;
    }
}

extern "C" void kernel_launch(void* const* d_in, const int* in_sizes, int n_in,
                              void* d_out, int out_size)
{
    const float* x    = (const float*)d_in[0];
    const float* Wt   = (const float*)d_in[1];
    const float* bias = (const float*)d_in[2];
    float*       out  = (float*)d_out;

    dim3 grid(HOUT_ / ROWS_CTA, B_);   // 37 x 16 = 592 CTAs
    dim3 block(256);                   // 8 warps, halves warp-aligned
    conv_bias_relu_kernel<<<grid, block>>>(x, Wt, bias, out);
}